// round 10
// baseline (speedup 1.0000x reference)
#include <cuda_runtime.h>
#include <cstdint>

// Problem constants
#define BATCH 1024
#define SEQ   512
#define NF    64
#define H     128
#define G4    512
#define NOUT  128

// Kernel config
#define M     8
#define NCTA  128
#define NTHR  512
#define RES0  8                // kg0 resident Whh rows: [0,8)
#define RES1  12               // kg1 resident Whh rows: [32,44)
#define NRES  (RES0 + RES1)    // 20

// smem layout (floats)
#define OFF_WIH   0                        // [64][512]
#define OFF_WHH   (64 * G4)                // [20][512]: 0..7 = Whh[0..7], 8..19 = Whh[32..43]
#define OFF_XD    (OFF_WHH + NRES * G4)    // ull [2][64][8]  (dup pairs) = 4096 floats
#define OFF_HD    (OFF_XD + 4096)          // ull [128][8]   (dup pairs) = 2048 floats
#define OFF_GB    (OFF_HD + 2048)          // [512][9]
#define OFF_PART  (OFF_GB + G4 * 9)        // ull [8][256] = 4096 floats
#define SMEM_FLOATS (OFF_PART + 4096)      // 57856
#define SMEM_BYTES  (SMEM_FLOATS * 4)      // 231424

typedef unsigned long long ull;

__device__ float g_WihT[NF * G4];          // [f][c]
__device__ float g_WhhT[(H + 4) * G4];     // [k][c], 4 pad rows for prefetch overfetch
__device__ float g_WoutT[H * NOUT];        // [k][oc]

// ---------------- packed f32x2 helpers ----------------
__device__ __forceinline__ void ffma2(ull& acc, ull a, ull b) {
    asm("fma.rn.f32x2 %0, %1, %2, %0;" : "+l"(acc) : "l"(a), "l"(b));
}
__device__ __forceinline__ ull fadd2(ull a, ull b) {
    ull r; asm("add.rn.f32x2 %0, %1, %2;" : "=l"(r) : "l"(a), "l"(b)); return r;
}
__device__ __forceinline__ ull pack2(float lo, float hi) {
    ull r; asm("mov.b64 %0, {%1, %2};" : "=l"(r) : "f"(lo), "f"(hi)); return r;
}
__device__ __forceinline__ void unpack2(ull v, float& lo, float& hi) {
    asm("mov.b64 {%0, %1}, %2;" : "=f"(lo), "=f"(hi) : "l"(v));
}

// ---------------- activations ----------------
__device__ __forceinline__ float ex2f(float x) { float r; asm("ex2.approx.f32 %0, %1;" : "=f"(r) : "f"(x)); return r; }
__device__ __forceinline__ float rcpf(float x) { float r; asm("rcp.approx.f32 %0, %1;" : "=f"(r) : "f"(x)); return r; }
__device__ __forceinline__ float sigmf(float x) {
    return rcpf(1.0f + ex2f(-1.4426950408889634f * x));
}
__device__ __forceinline__ float tanhf_acc(float x) {
    return fmaf(2.0f, rcpf(1.0f + ex2f(-2.8853900817779268f * x)), -1.0f);
}
__device__ __forceinline__ float act(float v, bool isTanh) {
    return isTanh ? tanhf_acc(v) : sigmf(v);
}

// ---------------- one-time weight transpose ----------------
__global__ void prep_kernel(const float* __restrict__ W_ih,
                            const float* __restrict__ W_hh,
                            const float* __restrict__ W_out) {
    int idx = blockIdx.x * blockDim.x + threadIdx.x;
    if (idx < (NF + H) * G4) {
        int k = idx / G4;
        int c = idx - k * G4;
        if (k < NF) g_WihT[idx]               = W_ih[c * NF + k];
        else        g_WhhT[(k - NF) * G4 + c] = W_hh[c * H + (k - NF)];
    } else {
        int j = idx - (NF + H) * G4;
        if (j < H * NOUT) {
            int k = j >> 7, oc = j & 127;
            g_WoutT[k * NOUT + oc] = W_out[oc * H + k];
        }
    }
}

// col-packed micro-step: acc_r (cols c0,c0+1) += dup(h_r) * w2, rows r=0..7
// SRC = ull* to 8 dup'd row pairs
#define STEPC(W2, SRC)                                              \
    do {                                                            \
        ulonglong2 hA = *(const ulonglong2*)(SRC);                  \
        ulonglong2 hB = *(const ulonglong2*)((SRC) + 2);            \
        ulonglong2 hC = *(const ulonglong2*)((SRC) + 4);            \
        ulonglong2 hD = *(const ulonglong2*)((SRC) + 6);            \
        ffma2(a0, hA.x, (W2)); ffma2(a1, hA.y, (W2));               \
        ffma2(a2, hB.x, (W2)); ffma2(a3, hB.y, (W2));               \
        ffma2(a4, hC.x, (W2)); ffma2(a5, hC.y, (W2));               \
        ffma2(a6, hD.x, (W2)); ffma2(a7, hD.y, (W2));               \
    } while (0)

// ---------------- persistent fused LSTM kernel ----------------
__global__ void __launch_bounds__(NTHR, 1)
lstm_kernel(const float* __restrict__ x,
            const float* __restrict__ b_ih, const float* __restrict__ b_hh,
            const float* __restrict__ b_out,
            float* __restrict__ out)
{
    extern __shared__ float sm[];
    float* Wih  = sm + OFF_WIH;
    float* Whh  = sm + OFF_WHH;
    ull*   xd   = (ull*)(sm + OFF_XD);     // [2][64][8] dup'd
    ull*   hds  = (ull*)(sm + OFF_HD);     // [128][8] dup'd
    float* gbuf = sm + OFF_GB;             // [512][9]
    ull*   part = (ull*)(sm + OFF_PART);   // [8][256]

    const int tid = threadIdx.x;
    const int b0  = blockIdx.x * M;

    const int cp = tid & 255;        // col pair index -> cols c0, c0+1
    const int c0 = 2 * cp;
    const int kg = tid >> 8;         // 0: x + h[0,32) ; 1: h[32,128)

    // ---- stage resident weights ----
    {
        const float4* s = (const float4*)g_WihT;
        float4*       d = (float4*)Wih;
        #pragma unroll
        for (int i = 0; i < (NF * G4 / 4) / NTHR; ++i) d[tid + i * NTHR] = s[tid + i * NTHR];
    }
    {   // sm rows 0..7 = Whh[0..7]; sm rows 8..19 = Whh[32..43]
        float4* d = (float4*)Whh;
        const float4* s0 = (const float4*)(g_WhhT);
        const float4* s1 = (const float4*)(g_WhhT + 32 * G4);
        for (int i = tid; i < RES0 * G4 / 4; i += NTHR) d[i] = s0[i];
        for (int i = tid; i < RES1 * G4 / 4; i += NTHR) d[RES0 * G4 / 4 + i] = s1[i];
    }
    for (int i = tid; i < H * M / 2; i += NTHR) ((ulonglong2*)hds)[i] = make_ulonglong2(0ull, 0ull);

    // x loader identity: feature lf = tid>>3, row lr = tid&7; store dup'd pair
    const int lf = tid >> 3, lr = tid & 7;
    const float* xp = x + ((size_t)(b0 + lr) * SEQ) * NF + lf;
    xd[lf * M + lr] = pack2(xp[0], xp[0]);       // buffer 0, t=0

    const ull bias2 = (kg == 0) ? pack2(b_ih[c0] + b_hh[c0], b_ih[c0 + 1] + b_hh[c0 + 1]) : 0ull;
    const bool isT = ((c0 >> 7) == 2);           // gate g, cols 256..383

    // phase-2 identity
    const int hc = tid & 127;
    const int a2 = (tid >> 7) * 2;               // rows a2, a2+1
    float cst0 = 0.f, cst1 = 0.f;

    __syncthreads();

    for (int t = 0; t < SEQ; ++t) {
        // prefetch x(t+1)
        float xpre = 0.f;
        const bool doPre = (t + 1 < SEQ);
        if (doPre) xpre = __ldg(xp + (size_t)(t + 1) * NF);

        ull a0 = bias2, a1 = bias2, a2r = bias2, a3 = bias2;
        ull a4 = bias2, a5 = bias2, a6 = bias2, a7 = bias2;
        // rename to match macro
        #define a2 a2r
        const ull* xsb = xd + (t & 1) * (NF * M);

        if (kg == 0) {
            // x-part: 64 rows, weights resident in smem
            #pragma unroll 4
            for (int j = 0; j < NF; ++j) {
                ull w2 = *(const ull*)(Wih + j * G4 + c0);
                STEPC(w2, xsb + j * M);
            }
            // h rows [0,8) resident
            #pragma unroll
            for (int k = 0; k < RES0; ++k) {
                ull w2 = *(const ull*)(Whh + k * G4 + c0);
                STEPC(w2, hds + k * M);
            }
            // h rows [8,32) streamed with depth-4 prefetch (overfetch hits rows 32..35, valid)
            {
                const ull* wg = (const ull*)(g_WhhT + RES0 * G4) + cp;
                ull w0 = __ldg(wg), w1 = __ldg(wg + 256), w2p = __ldg(wg + 512), w3 = __ldg(wg + 768);
                wg += 1024;
                #pragma unroll
                for (int k = RES0; k < 32; k += 4) {
                    ull u0 = w0, u1 = w1, u2 = w2p, u3 = w3;
                    w0 = __ldg(wg); w1 = __ldg(wg + 256); w2p = __ldg(wg + 512); w3 = __ldg(wg + 768);
                    wg += 1024;
                    STEPC(u0, hds + (k + 0) * M);
                    STEPC(u1, hds + (k + 1) * M);
                    STEPC(u2, hds + (k + 2) * M);
                    STEPC(u3, hds + (k + 3) * M);
                }
            }
        } else {
            // h rows [32,44) resident
            #pragma unroll
            for (int k = 0; k < RES1; ++k) {
                ull w2 = *(const ull*)(Whh + (RES0 + k) * G4 + c0);
                STEPC(w2, hds + (32 + k) * M);
            }
            // h rows [44,128) streamed with depth-4 prefetch (overfetch hits pad rows 128..131)
            {
                const ull* wg = (const ull*)(g_WhhT + 44 * G4) + cp;
                ull w0 = __ldg(wg), w1 = __ldg(wg + 256), w2p = __ldg(wg + 512), w3 = __ldg(wg + 768);
                wg += 1024;
                #pragma unroll 3
                for (int k = 44; k < H; k += 4) {
                    ull u0 = w0, u1 = w1, u2 = w2p, u3 = w3;
                    w0 = __ldg(wg); w1 = __ldg(wg + 256); w2p = __ldg(wg + 512); w3 = __ldg(wg + 768);
                    wg += 1024;
                    STEPC(u0, hds + (k + 0) * M);
                    STEPC(u1, hds + (k + 1) * M);
                    STEPC(u2, hds + (k + 2) * M);
                    STEPC(u3, hds + (k + 3) * M);
                }
            }
        }
        #undef a2

        if (kg == 1) {
            ull* pb = part + cp;
            pb[0 * 256] = a0;  pb[1 * 256] = a1;  pb[2 * 256] = a2r; pb[3 * 256] = a3;
            pb[4 * 256] = a4;  pb[5 * 256] = a5;  pb[6 * 256] = a6;  pb[7 * 256] = a7;
        }
        // stage x(t+1) dup'd into the other buffer
        if (doPre) xd[((t + 1) & 1) * (NF * M) + lf * M + lr] = pack2(xpre, xpre);

        __syncthreads();   // B1: partials + xd staged

        if (kg == 0) {
            const ull* pb = part + cp;
            a0  = fadd2(a0,  pb[0 * 256]); a1 = fadd2(a1, pb[1 * 256]);
            a2r = fadd2(a2r, pb[2 * 256]); a3 = fadd2(a3, pb[3 * 256]);
            a4  = fadd2(a4,  pb[4 * 256]); a5 = fadd2(a5, pb[5 * 256]);
            a6  = fadd2(a6,  pb[6 * 256]); a7 = fadd2(a7, pb[7 * 256]);

            float v0, v1;
            float* g0 = gbuf + c0 * 9;       // col c0, rows 0..7
            float* g1 = g0 + 9;              // col c0+1
            unpack2(a0,  v0, v1); g0[0] = act(v0, isT); g1[0] = act(v1, isT);
            unpack2(a1,  v0, v1); g0[1] = act(v0, isT); g1[1] = act(v1, isT);
            unpack2(a2r, v0, v1); g0[2] = act(v0, isT); g1[2] = act(v1, isT);
            unpack2(a3,  v0, v1); g0[3] = act(v0, isT); g1[3] = act(v1, isT);
            unpack2(a4,  v0, v1); g0[4] = act(v0, isT); g1[4] = act(v1, isT);
            unpack2(a5,  v0, v1); g0[5] = act(v0, isT); g1[5] = act(v1, isT);
            unpack2(a6,  v0, v1); g0[6] = act(v0, isT); g1[6] = act(v1, isT);
            unpack2(a7,  v0, v1); g0[7] = act(v0, isT); g1[7] = act(v1, isT);
        }
        __syncthreads();   // B2: gbuf(t) ready

        // phase 2: update (hc, rows a2, a2+1); write dup'd h
        {
            const float* gi = gbuf + hc * 9;
            const float* gf = gi + 128 * 9;
            const float* gg = gi + 256 * 9;
            const float* go = gi + 384 * 9;
            float i0 = gi[a2],     f0 = gf[a2],     gv0 = gg[a2],     o0 = go[a2];
            float i1 = gi[a2 + 1], f1 = gf[a2 + 1], gv1 = gg[a2 + 1], o1 = go[a2 + 1];
            cst0 = fmaf(f0, cst0, i0 * gv0);
            cst1 = fmaf(f1, cst1, i1 * gv1);
            float h0 = o0 * tanhf_acc(cst0);
            float h1 = o1 * tanhf_acc(cst1);
            *(ulonglong2*)(hds + hc * M + a2) = make_ulonglong2(pack2(h0, h0), pack2(h1, h1));
        }
        __syncthreads();   // B3: hd(t) ready
    }

    // output projection: thread (oc, rows rr, rr+4); hds holds dup'd pairs
    {
        const int oc = tid & 127;
        const int rr = tid >> 7;
        float acc0 = b_out[oc], acc1 = acc0;
        const float* wt = g_WoutT + oc;
        const float* hf = (const float*)hds;
        #pragma unroll 8
        for (int k = 0; k < H; ++k) {
            float w = __ldg(wt + k * NOUT);
            acc0 = fmaf(w, hf[(k * M + rr) * 2], acc0);
            acc1 = fmaf(w, hf[(k * M + rr + 4) * 2], acc1);
        }
        out[(size_t)(b0 + rr) * NOUT + oc]     = acc0;
        out[(size_t)(b0 + rr + 4) * NOUT + oc] = acc1;
    }
}

extern "C" void kernel_launch(void* const* d_in, const int* in_sizes, int n_in,
                              void* d_out, int out_size)
{
    const float* x     = (const float*)d_in[0];
    const float* W_ih  = (const float*)d_in[1];
    const float* W_hh  = (const float*)d_in[2];
    const float* b_ih  = (const float*)d_in[3];
    const float* b_hh  = (const float*)d_in[4];
    const float* W_out = (const float*)d_in[5];
    const float* b_out = (const float*)d_in[6];
    float* out = (float*)d_out;

    const int prep_n = (NF + H) * G4 + H * NOUT;
    prep_kernel<<<(prep_n + 255) / 256, 256>>>(W_ih, W_hh, W_out);

    cudaFuncSetAttribute(lstm_kernel,
                         cudaFuncAttributeMaxDynamicSharedMemorySize, SMEM_BYTES);
    lstm_kernel<<<NCTA, NTHR, SMEM_BYTES>>>(x, b_ih, b_hh, b_out, out);
}

// round 12
// speedup vs baseline: 1.4596x; 1.4596x over previous
#include <cuda_runtime.h>
#include <cstdint>

// Problem constants
#define BATCH 1024
#define SEQ   512
#define NF    64
#define H     128
#define G4    512
#define NOUT  128

// Kernel config
#define M     8
#define NCTA  128
#define NTHR  512
#define RES0  8                // kg0 resident Whh rows: [0,8)   (streams [8,32) = 24)
#define RES1  16               // kg1 resident Whh rows: [32,48) (streams [48,128) = 80)

// smem layout (floats)
#define OFF_WIH   0                        // [64][512]
#define OFF_WHH   (64 * G4)                // [24][512]: 0..7 = Whh[0..7], 8..23 = Whh[32..47]
#define OFF_XD    (OFF_WHH + 24 * G4)      // [2][64][8]
#define OFF_HD    (OFF_XD + 2 * NF * M)    // [128][8]
#define OFF_PART  (OFF_HD + H * M)         // [2][8][512] floats (raw gate partials, [kg][row][col])
#define SMEM_FLOATS (OFF_PART + 2 * 8 * G4)   // 55296
#define SMEM_BYTES  (SMEM_FLOATS * 4)         // 221184

typedef unsigned long long ull;

__device__ float g_WihT[NF * G4];          // [f][c]
__device__ float g_WhhT[(H + 4) * G4];     // [k][c], +4 pad rows for prefetch overfetch
__device__ float g_WoutT[H * NOUT];        // [k][oc]

// ---------------- packed f32x2 helpers ----------------
__device__ __forceinline__ void ffma2(ull& acc, ull a, ull b) {
    asm("fma.rn.f32x2 %0, %1, %2, %0;" : "+l"(acc) : "l"(a), "l"(b));
}
__device__ __forceinline__ ull pack2(float lo, float hi) {
    ull r; asm("mov.b64 %0, {%1, %2};" : "=l"(r) : "f"(lo), "f"(hi)); return r;
}
__device__ __forceinline__ void unpack2(ull v, float& lo, float& hi) {
    asm("mov.b64 {%0, %1}, %2;" : "=f"(lo), "=f"(hi) : "l"(v));
}
__device__ __forceinline__ void dup2(ull w2, ull& d0, ull& d1) {
    asm("{\n\t"
        ".reg .f32 w0, w1;\n\t"
        "mov.b64 {w0, w1}, %2;\n\t"
        "mov.b64 %0, {w0, w0};\n\t"
        "mov.b64 %1, {w1, w1};\n\t"
        "}" : "=l"(d0), "=l"(d1) : "l"(w2));
}

// ---------------- activations ----------------
__device__ __forceinline__ float ex2f(float x) { float r; asm("ex2.approx.f32 %0, %1;" : "=f"(r) : "f"(x)); return r; }
__device__ __forceinline__ float rcpf(float x) { float r; asm("rcp.approx.f32 %0, %1;" : "=f"(r) : "f"(x)); return r; }
__device__ __forceinline__ float sigmf(float x) {
    return rcpf(1.0f + ex2f(-1.4426950408889634f * x));
}
__device__ __forceinline__ float tanhf_acc(float x) {
    return fmaf(2.0f, rcpf(1.0f + ex2f(-2.8853900817779268f * x)), -1.0f);
}

// ---------------- one-time weight transpose ----------------
__global__ void prep_kernel(const float* __restrict__ W_ih,
                            const float* __restrict__ W_hh,
                            const float* __restrict__ W_out) {
    int idx = blockIdx.x * blockDim.x + threadIdx.x;
    if (idx < (NF + H) * G4) {
        int k = idx / G4;
        int c = idx - k * G4;
        if (k < NF) g_WihT[idx]               = W_ih[c * NF + k];
        else        g_WhhT[(k - NF) * G4 + c] = W_hh[c * H + (k - NF)];
    } else {
        int j = idx - (NF + H) * G4;
        if (j < H * NOUT) {
            int k = j >> 7, oc = j & 127;
            g_WoutT[k * NOUT + oc] = W_out[oc * H + k];
        }
    }
}

// row-packed micro-step: a0..a3 = col c0 rowpairs, b0..b3 = col c0+1 rowpairs
#define STEPW(W2, SRC)                                                  \
    do {                                                                \
        ull d0, d1; dup2((W2), d0, d1);                                 \
        ulonglong2 hA = *(const ulonglong2*)(SRC);                      \
        ulonglong2 hB = *(const ulonglong2*)((SRC) + 4);                \
        ffma2(a0, hA.x, d0); ffma2(a1, hA.y, d0);                       \
        ffma2(a2, hB.x, d0); ffma2(a3, hB.y, d0);                       \
        ffma2(b0, hA.x, d1); ffma2(b1, hA.y, d1);                       \
        ffma2(b2, hB.x, d1); ffma2(b3, hB.y, d1);                       \
    } while (0)

// ---------------- persistent fused LSTM kernel ----------------
__global__ void __launch_bounds__(NTHR, 1)
lstm_kernel(const float* __restrict__ x,
            const float* __restrict__ b_ih, const float* __restrict__ b_hh,
            const float* __restrict__ b_out,
            float* __restrict__ out)
{
    extern __shared__ float sm[];
    float* Wih  = sm + OFF_WIH;
    float* Whh  = sm + OFF_WHH;
    float* xd   = sm + OFF_XD;             // [2][64][8]
    float* hd   = sm + OFF_HD;             // [128][8]
    float* pf   = sm + OFF_PART;           // [2][8][512]
    ull*   pu   = (ull*)pf;                // [2][8][256]

    const int tid = threadIdx.x;
    const int b0  = blockIdx.x * M;

    const int cp = tid & 255;
    const int c0 = 2 * cp;
    const int kg = tid >> 8;               // 0: x + h[0,32) ; 1: h[32,128)

    // ---- stage resident weights ----
    {
        const float4* s = (const float4*)g_WihT;
        float4*       d = (float4*)Wih;
        #pragma unroll
        for (int i = 0; i < (NF * G4 / 4) / NTHR; ++i) d[tid + i * NTHR] = s[tid + i * NTHR];
    }
    {   // sm rows 0..7 = Whh[0..7]; sm rows 8..23 = Whh[32..47]
        float4* d = (float4*)Whh;
        const float4* s0 = (const float4*)(g_WhhT);
        const float4* s1 = (const float4*)(g_WhhT + 32 * G4);
        for (int i = tid; i < RES0 * G4 / 4; i += NTHR) d[i] = s0[i];
        for (int i = tid; i < RES1 * G4 / 4; i += NTHR) d[RES0 * G4 / 4 + i] = s1[i];
    }
    for (int i = tid; i < H * M; i += NTHR) hd[i] = 0.0f;

    // x loader: feature lf = tid>>3, row lr = tid&7
    const int lf = tid >> 3, lr = tid & 7;
    const float* xp = x + ((size_t)(b0 + lr) * SEQ) * NF + lf;
    xd[lf * M + lr] = xp[0];               // buffer 0, t=0

    // bias (kg0 only)
    ull bias0 = 0ull, bias1 = 0ull;
    if (kg == 0) {
        float bb0 = b_ih[c0] + b_hh[c0];
        float bb1 = b_ih[c0 + 1] + b_hh[c0 + 1];
        bias0 = pack2(bb0, bb0);
        bias1 = pack2(bb1, bb1);
    }

    // phase-2 identity: col hc, rows rb, rb+1
    const int hc = tid & 127;
    const int rb = (tid >> 7) * 2;
    float cs0 = 0.f, cs1 = 0.f;

    __syncthreads();

    for (int t = 0; t < SEQ; ++t) {
        // prefetch x(t+1)
        float xpre = 0.f;
        const bool doPre = (t + 1 < SEQ);
        if (doPre) xpre = __ldg(xp + (size_t)(t + 1) * NF);

        ull a0 = bias0, a1 = bias0, a2 = bias0, a3 = bias0;
        ull b0r = bias1, b1r = bias1, b2r = bias1, b3r = bias1;
        #define b0 b0r
        #define b1 b1r
        #define b2 b2r
        #define b3 b3r

        const float* xsb = xd + (t & 1) * (NF * M);

        if (kg == 0) {
            // x-part: 64 rows, resident
            #pragma unroll 8
            for (int j = 0; j < NF; ++j) {
                ull w2 = *(const ull*)(Wih + j * G4 + c0);
                STEPW(w2, xsb + j * M);
            }
            // h rows [0,8): resident
            #pragma unroll
            for (int k = 0; k < RES0; ++k) {
                ull w2 = *(const ull*)(Whh + k * G4 + c0);
                STEPW(w2, hd + k * M);
            }
            // h rows [8,32): streamed, depth-4 rotation (overfetch rows 32..35 valid)
            {
                const ull* wg = (const ull*)(g_WhhT + RES0 * G4) + cp;
                ull w0 = __ldg(wg), w1 = __ldg(wg + 256), w2p = __ldg(wg + 512), w3 = __ldg(wg + 768);
                wg += 1024;
                #pragma unroll
                for (int k = RES0; k < 32; k += 4) {
                    ull u0 = w0, u1 = w1, u2 = w2p, u3 = w3;
                    w0 = __ldg(wg); w1 = __ldg(wg + 256); w2p = __ldg(wg + 512); w3 = __ldg(wg + 768);
                    wg += 1024;
                    STEPW(u0, hd + (k + 0) * M);
                    STEPW(u1, hd + (k + 1) * M);
                    STEPW(u2, hd + (k + 2) * M);
                    STEPW(u3, hd + (k + 3) * M);
                }
            }
        } else {
            // h rows [32,48): resident
            #pragma unroll
            for (int k = 0; k < RES1; ++k) {
                ull w2 = *(const ull*)(Whh + (RES0 + k) * G4 + c0);
                STEPW(w2, hd + (32 + k) * M);
            }
            // h rows [48,128): streamed, depth-4 rotation (overfetch pad rows 128..131)
            {
                const ull* wg = (const ull*)(g_WhhT + 48 * G4) + cp;
                ull w0 = __ldg(wg), w1 = __ldg(wg + 256), w2p = __ldg(wg + 512), w3 = __ldg(wg + 768);
                wg += 1024;
                #pragma unroll 5
                for (int k = 48; k < H; k += 4) {
                    ull u0 = w0, u1 = w1, u2 = w2p, u3 = w3;
                    w0 = __ldg(wg); w1 = __ldg(wg + 256); w2p = __ldg(wg + 512); w3 = __ldg(wg + 768);
                    wg += 1024;
                    STEPW(u0, hd + (k + 0) * M);
                    STEPW(u1, hd + (k + 1) * M);
                    STEPW(u2, hd + (k + 2) * M);
                    STEPW(u3, hd + (k + 3) * M);
                }
            }
        }
        #undef b0
        #undef b1
        #undef b2
        #undef b3

        // transpose accumulators and store raw partials: pf[kg][r][c]
        {
            ull* pb = pu + kg * 8 * 256 + cp;
            float x0, x1, y0, y1;
            unpack2(a0, x0, x1); unpack2(b0r, y0, y1);
            pb[0 * 256] = pack2(x0, y0); pb[1 * 256] = pack2(x1, y1);
            unpack2(a1, x0, x1); unpack2(b1r, y0, y1);
            pb[2 * 256] = pack2(x0, y0); pb[3 * 256] = pack2(x1, y1);
            unpack2(a2, x0, x1); unpack2(b2r, y0, y1);
            pb[4 * 256] = pack2(x0, y0); pb[5 * 256] = pack2(x1, y1);
            unpack2(a3, x0, x1); unpack2(b3r, y0, y1);
            pb[6 * 256] = pack2(x0, y0); pb[7 * 256] = pack2(x1, y1);
        }
        // stage x(t+1)
        if (doPre) xd[((t + 1) & 1) * (NF * M) + lf * M + lr] = xpre;

        __syncthreads();   // B1: partials + xd staged

        // phase 2 (all 512 threads): sum partials, activate, update state
        {
            const float* p0 = pf + (0 * 8 + rb) * G4;
            const float* p1 = pf + (8 + rb) * G4;
            float si0 = p0[hc]       + p1[hc];
            float sf0 = p0[hc + 128] + p1[hc + 128];
            float sg0 = p0[hc + 256] + p1[hc + 256];
            float so0 = p0[hc + 384] + p1[hc + 384];
            const float* q0 = p0 + G4;
            const float* q1 = p1 + G4;
            float si1 = q0[hc]       + q1[hc];
            float sf1 = q0[hc + 128] + q1[hc + 128];
            float sg1 = q0[hc + 256] + q1[hc + 256];
            float so1 = q0[hc + 384] + q1[hc + 384];

            float iv0 = sigmf(si0), fv0 = sigmf(sf0), gv0 = tanhf_acc(sg0), ov0 = sigmf(so0);
            float iv1 = sigmf(si1), fv1 = sigmf(sf1), gv1 = tanhf_acc(sg1), ov1 = sigmf(so1);
            cs0 = fmaf(fv0, cs0, iv0 * gv0);
            cs1 = fmaf(fv1, cs1, iv1 * gv1);
            float h0 = ov0 * tanhf_acc(cs0);
            float h1 = ov1 * tanhf_acc(cs1);
            *(ull*)(hd + hc * M + rb) = pack2(h0, h1);
        }
        __syncthreads();   // B2: hd(t) ready
    }

    // output projection: thread (oc, rows rr, rr+4)
    {
        const int oc = tid & 127;
        const int rr = tid >> 7;
        float acc0 = b_out[oc], acc1 = acc0;
        const float* wt = g_WoutT + oc;
        #pragma unroll 8
        for (int k = 0; k < H; ++k) {
            float w = __ldg(wt + k * NOUT);
            acc0 = fmaf(w, hd[k * M + rr], acc0);
            acc1 = fmaf(w, hd[k * M + rr + 4], acc1);
        }
        out[(size_t)(b0 + rr) * NOUT + oc]     = acc0;
        out[(size_t)(b0 + rr + 4) * NOUT + oc] = acc1;
    }
}

extern "C" void kernel_launch(void* const* d_in, const int* in_sizes, int n_in,
                              void* d_out, int out_size)
{
    const float* x     = (const float*)d_in[0];
    const float* W_ih  = (const float*)d_in[1];
    const float* W_hh  = (const float*)d_in[2];
    const float* b_ih  = (const float*)d_in[3];
    const float* b_hh  = (const float*)d_in[4];
    const float* W_out = (const float*)d_in[5];
    const float* b_out = (const float*)d_in[6];
    float* out = (float*)d_out;

    const int prep_n = (NF + H) * G4 + H * NOUT;
    prep_kernel<<<(prep_n + 255) / 256, 256>>>(W_ih, W_hh, W_out);

    cudaFuncSetAttribute(lstm_kernel,
                         cudaFuncAttributeMaxDynamicSharedMemorySize, SMEM_BYTES);
    lstm_kernel<<<NCTA, NTHR, SMEM_BYTES>>>(x, b_ih, b_hh, b_out, out);
}

// round 13
// speedup vs baseline: 1.5233x; 1.0437x over previous
#include <cuda_runtime.h>
#include <cstdint>

// Problem constants
#define BATCH 1024
#define SEQ   512
#define NF    64
#define H     128
#define G4    512
#define NOUT  128

// Kernel config
#define M     8
#define NCTA  128
#define NTHR  512
#define RES0  8                // kg0 resident Whh rows: [0,8)   (streams [8,32) = 24)
#define RES1  16               // kg1 resident Whh rows: [32,48) (streams [48,128) = 80)

// smem layout (floats)
#define OFF_WIH   0                        // [64][512]
#define OFF_WHH   (64 * G4)                // [24][512]: 0..7 = Whh[0..7], 8..23 = Whh[32..47]
#define OFF_XD    (OFF_WHH + 24 * G4)      // [2][64][8]
#define OFF_HD    (OFF_XD + 2 * NF * M)    // [128][8]
#define OFF_PART  (OFF_HD + H * M)         // [2][8][512] floats (raw gate partials)
#define SMEM_FLOATS (OFF_PART + 2 * 8 * G4)   // 55296
#define SMEM_BYTES  (SMEM_FLOATS * 4)         // 221184

typedef unsigned long long ull;

__device__ float g_WihT[NF * G4];          // [f][c]
__device__ float g_WhhT[(H + 8) * G4];     // [k][c], +8 pad rows for ring overfetch
__device__ float g_WoutT[H * NOUT];        // [k][oc]

// ---------------- packed f32x2 helpers ----------------
__device__ __forceinline__ void ffma2(ull& acc, ull a, ull b) {
    asm("fma.rn.f32x2 %0, %1, %2, %0;" : "+l"(acc) : "l"(a), "l"(b));
}
__device__ __forceinline__ ull pack2(float lo, float hi) {
    ull r; asm("mov.b64 %0, {%1, %2};" : "=l"(r) : "f"(lo), "f"(hi)); return r;
}
__device__ __forceinline__ void unpack2(ull v, float& lo, float& hi) {
    asm("mov.b64 {%0, %1}, %2;" : "=f"(lo), "=f"(hi) : "l"(v));
}
__device__ __forceinline__ void dup2(ull w2, ull& d0, ull& d1) {
    asm("{\n\t"
        ".reg .f32 w0, w1;\n\t"
        "mov.b64 {w0, w1}, %2;\n\t"
        "mov.b64 %0, {w0, w0};\n\t"
        "mov.b64 %1, {w1, w1};\n\t"
        "}" : "=l"(d0), "=l"(d1) : "l"(w2));
}

// ---------------- activations ----------------
__device__ __forceinline__ float ex2f(float x) { float r; asm("ex2.approx.f32 %0, %1;" : "=f"(r) : "f"(x)); return r; }
__device__ __forceinline__ float rcpf(float x) { float r; asm("rcp.approx.f32 %0, %1;" : "=f"(r) : "f"(x)); return r; }
__device__ __forceinline__ float sigmf(float x) {
    return rcpf(1.0f + ex2f(-1.4426950408889634f * x));
}
__device__ __forceinline__ float tanhf_acc(float x) {
    return fmaf(2.0f, rcpf(1.0f + ex2f(-2.8853900817779268f * x)), -1.0f);
}

// ---------------- one-time weight transpose ----------------
__global__ void prep_kernel(const float* __restrict__ W_ih,
                            const float* __restrict__ W_hh,
                            const float* __restrict__ W_out) {
    int idx = blockIdx.x * blockDim.x + threadIdx.x;
    if (idx < (NF + H) * G4) {
        int k = idx / G4;
        int c = idx - k * G4;
        if (k < NF) g_WihT[idx]               = W_ih[c * NF + k];
        else        g_WhhT[(k - NF) * G4 + c] = W_hh[c * H + (k - NF)];
    } else {
        int j = idx - (NF + H) * G4;
        if (j < H * NOUT) {
            int k = j >> 7, oc = j & 127;
            g_WoutT[k * NOUT + oc] = W_out[oc * H + k];
        }
    }
}

// row-packed micro-step: a0..a3 = col c0 rowpairs, b0..b3 = col c0+1 rowpairs
#define STEPW(W2, SRC)                                                  \
    do {                                                                \
        ull d0, d1; dup2((W2), d0, d1);                                 \
        ulonglong2 hA = *(const ulonglong2*)(SRC);                      \
        ulonglong2 hB = *(const ulonglong2*)((SRC) + 4);                \
        ffma2(a0, hA.x, d0); ffma2(a1, hA.y, d0);                       \
        ffma2(a2, hB.x, d0); ffma2(a3, hB.y, d0);                       \
        ffma2(b0, hA.x, d1); ffma2(b1, hA.y, d1);                       \
        ffma2(b2, hB.x, d1); ffma2(b3, hB.y, d1);                       \
    } while (0)

// ---------------- persistent fused LSTM kernel ----------------
__global__ void __launch_bounds__(NTHR, 1)
lstm_kernel(const float* __restrict__ x,
            const float* __restrict__ b_ih, const float* __restrict__ b_hh,
            const float* __restrict__ b_out,
            float* __restrict__ out)
{
    extern __shared__ float sm[];
    float* Wih  = sm + OFF_WIH;
    float* Whh  = sm + OFF_WHH;
    float* xd   = sm + OFF_XD;             // [2][64][8]
    float* hd   = sm + OFF_HD;             // [128][8]
    float* pf   = sm + OFF_PART;           // [2][8][512]
    ull*   pu   = (ull*)pf;                // [2][8][256]

    const int tid = threadIdx.x;
    const int b0  = blockIdx.x * M;

    const int cp = tid & 255;
    const int c0 = 2 * cp;
    const int kg = tid >> 8;               // 0: x + h[0,32) ; 1: h[32,128)

    // ---- stage resident weights ----
    {
        const float4* s = (const float4*)g_WihT;
        float4*       d = (float4*)Wih;
        #pragma unroll
        for (int i = 0; i < (NF * G4 / 4) / NTHR; ++i) d[tid + i * NTHR] = s[tid + i * NTHR];
    }
    {   // sm rows 0..7 = Whh[0..7]; sm rows 8..23 = Whh[32..47]
        float4* d = (float4*)Whh;
        const float4* s0 = (const float4*)(g_WhhT);
        const float4* s1 = (const float4*)(g_WhhT + 32 * G4);
        for (int i = tid; i < RES0 * G4 / 4; i += NTHR) d[i] = s0[i];
        for (int i = tid; i < RES1 * G4 / 4; i += NTHR) d[RES0 * G4 / 4 + i] = s1[i];
    }
    for (int i = tid; i < H * M; i += NTHR) hd[i] = 0.0f;

    // x loader: feature lf = tid>>3, row lr = tid&7
    const int lf = tid >> 3, lr = tid & 7;
    const float* xp = x + ((size_t)(b0 + lr) * SEQ) * NF + lf;
    xd[lf * M + lr] = xp[0];               // buffer 0, t=0

    // bias (kg0 only)
    ull bias0 = 0ull, bias1 = 0ull;
    if (kg == 0) {
        float bb0 = b_ih[c0] + b_hh[c0];
        float bb1 = b_ih[c0 + 1] + b_hh[c0 + 1];
        bias0 = pack2(bb0, bb0);
        bias1 = pack2(bb1, bb1);
    }

    // phase-2 identity: col hc, rows rb, rb+1
    const int hc = tid & 127;
    const int rb = (tid >> 7) * 2;
    float cs0 = 0.f, cs1 = 0.f;

    __syncthreads();

    for (int t = 0; t < SEQ; ++t) {
        // prefetch x(t+1)
        float xpre = 0.f;
        const bool doPre = (t + 1 < SEQ);
        if (doPre) xpre = __ldg(xp + (size_t)(t + 1) * NF);

        ull a0 = bias0, a1 = bias0, a2 = bias0, a3 = bias0;
        ull b0r = bias1, b1r = bias1, b2r = bias1, b3r = bias1;
        #define b0 b0r
        #define b1 b1r
        #define b2 b2r
        #define b3 b3r

        const float* xsb = xd + (t & 1) * (NF * M);

        if (kg == 0) {
            // x-part: 64 rows, resident
            #pragma unroll 8
            for (int j = 0; j < NF; ++j) {
                ull w2 = *(const ull*)(Wih + j * G4 + c0);
                STEPW(w2, xsb + j * M);
            }
            // ring preload for streamed rows [8,16) (covered by resident compute below)
            const ull* wg = (const ull*)(g_WhhT + RES0 * G4) + cp;
            ull u0 = __ldg(wg + 0 * 256), u1 = __ldg(wg + 1 * 256),
                u2 = __ldg(wg + 2 * 256), u3 = __ldg(wg + 3 * 256),
                u4 = __ldg(wg + 4 * 256), u5 = __ldg(wg + 5 * 256),
                u6 = __ldg(wg + 6 * 256), u7 = __ldg(wg + 7 * 256);
            wg += 8 * 256;
            // h rows [0,8): resident
            #pragma unroll
            for (int k = 0; k < RES0; ++k) {
                ull w2 = *(const ull*)(Whh + k * G4 + c0);
                STEPW(w2, hd + k * M);
            }
            // h rows [8,32): streamed, depth-8 ring (overfetch rows 32..39, valid)
            #pragma unroll
            for (int k = RES0; k < 32; k += 8) {
                STEPW(u0, hd + (k + 0) * M); u0 = __ldg(wg + 0 * 256);
                STEPW(u1, hd + (k + 1) * M); u1 = __ldg(wg + 1 * 256);
                STEPW(u2, hd + (k + 2) * M); u2 = __ldg(wg + 2 * 256);
                STEPW(u3, hd + (k + 3) * M); u3 = __ldg(wg + 3 * 256);
                STEPW(u4, hd + (k + 4) * M); u4 = __ldg(wg + 4 * 256);
                STEPW(u5, hd + (k + 5) * M); u5 = __ldg(wg + 5 * 256);
                STEPW(u6, hd + (k + 6) * M); u6 = __ldg(wg + 6 * 256);
                STEPW(u7, hd + (k + 7) * M); u7 = __ldg(wg + 7 * 256);
                wg += 8 * 256;
            }
        } else {
            // ring preload for streamed rows [48,56) (covered by resident compute below)
            const ull* wg = (const ull*)(g_WhhT + 48 * G4) + cp;
            ull u0 = __ldg(wg + 0 * 256), u1 = __ldg(wg + 1 * 256),
                u2 = __ldg(wg + 2 * 256), u3 = __ldg(wg + 3 * 256),
                u4 = __ldg(wg + 4 * 256), u5 = __ldg(wg + 5 * 256),
                u6 = __ldg(wg + 6 * 256), u7 = __ldg(wg + 7 * 256);
            wg += 8 * 256;
            // h rows [32,48): resident
            #pragma unroll
            for (int k = 0; k < RES1; ++k) {
                ull w2 = *(const ull*)(Whh + (RES0 + k) * G4 + c0);
                STEPW(w2, hd + (32 + k) * M);
            }
            // h rows [48,128): streamed, depth-8 ring (overfetch rows 128..135, padded)
            #pragma unroll
            for (int k = 48; k < H; k += 8) {
                STEPW(u0, hd + (k + 0) * M); u0 = __ldg(wg + 0 * 256);
                STEPW(u1, hd + (k + 1) * M); u1 = __ldg(wg + 1 * 256);
                STEPW(u2, hd + (k + 2) * M); u2 = __ldg(wg + 2 * 256);
                STEPW(u3, hd + (k + 3) * M); u3 = __ldg(wg + 3 * 256);
                STEPW(u4, hd + (k + 4) * M); u4 = __ldg(wg + 4 * 256);
                STEPW(u5, hd + (k + 5) * M); u5 = __ldg(wg + 5 * 256);
                STEPW(u6, hd + (k + 6) * M); u6 = __ldg(wg + 6 * 256);
                STEPW(u7, hd + (k + 7) * M); u7 = __ldg(wg + 7 * 256);
                wg += 8 * 256;
            }
        }
        #undef b0
        #undef b1
        #undef b2
        #undef b3

        // transpose accumulators and store raw partials: pf[kg][r][c]
        {
            ull* pb = pu + kg * 8 * 256 + cp;
            float x0, x1, y0, y1;
            unpack2(a0, x0, x1); unpack2(b0r, y0, y1);
            pb[0 * 256] = pack2(x0, y0); pb[1 * 256] = pack2(x1, y1);
            unpack2(a1, x0, x1); unpack2(b1r, y0, y1);
            pb[2 * 256] = pack2(x0, y0); pb[3 * 256] = pack2(x1, y1);
            unpack2(a2, x0, x1); unpack2(b2r, y0, y1);
            pb[4 * 256] = pack2(x0, y0); pb[5 * 256] = pack2(x1, y1);
            unpack2(a3, x0, x1); unpack2(b3r, y0, y1);
            pb[6 * 256] = pack2(x0, y0); pb[7 * 256] = pack2(x1, y1);
        }
        // stage x(t+1)
        if (doPre) xd[((t + 1) & 1) * (NF * M) + lf * M + lr] = xpre;

        __syncthreads();   // B1: partials + xd staged

        // phase 2 (all 512 threads): sum partials, activate, update state
        {
            const float* p0 = pf + (0 * 8 + rb) * G4;
            const float* p1 = pf + (8 + rb) * G4;
            float si0 = p0[hc]       + p1[hc];
            float sf0 = p0[hc + 128] + p1[hc + 128];
            float sg0 = p0[hc + 256] + p1[hc + 256];
            float so0 = p0[hc + 384] + p1[hc + 384];
            const float* q0 = p0 + G4;
            const float* q1 = p1 + G4;
            float si1 = q0[hc]       + q1[hc];
            float sf1 = q0[hc + 128] + q1[hc + 128];
            float sg1 = q0[hc + 256] + q1[hc + 256];
            float so1 = q0[hc + 384] + q1[hc + 384];

            float iv0 = sigmf(si0), fv0 = sigmf(sf0), gv0 = tanhf_acc(sg0), ov0 = sigmf(so0);
            float iv1 = sigmf(si1), fv1 = sigmf(sf1), gv1 = tanhf_acc(sg1), ov1 = sigmf(so1);
            cs0 = fmaf(fv0, cs0, iv0 * gv0);
            cs1 = fmaf(fv1, cs1, iv1 * gv1);
            float h0 = ov0 * tanhf_acc(cs0);
            float h1 = ov1 * tanhf_acc(cs1);
            *(ull*)(hd + hc * M + rb) = pack2(h0, h1);
        }
        __syncthreads();   // B2: hd(t) ready
    }

    // output projection: thread (oc, rows rr, rr+4)
    {
        const int oc = tid & 127;
        const int rr = tid >> 7;
        float acc0 = b_out[oc], acc1 = acc0;
        const float* wt = g_WoutT + oc;
        #pragma unroll 8
        for (int k = 0; k < H; ++k) {
            float w = __ldg(wt + k * NOUT);
            acc0 = fmaf(w, hd[k * M + rr], acc0);
            acc1 = fmaf(w, hd[k * M + rr + 4], acc1);
        }
        out[(size_t)(b0 + rr) * NOUT + oc]     = acc0;
        out[(size_t)(b0 + rr + 4) * NOUT + oc] = acc1;
    }
}

extern "C" void kernel_launch(void* const* d_in, const int* in_sizes, int n_in,
                              void* d_out, int out_size)
{
    const float* x     = (const float*)d_in[0];
    const float* W_ih  = (const float*)d_in[1];
    const float* W_hh  = (const float*)d_in[2];
    const float* b_ih  = (const float*)d_in[3];
    const float* b_hh  = (const float*)d_in[4];
    const float* W_out = (const float*)d_in[5];
    const float* b_out = (const float*)d_in[6];
    float* out = (float*)d_out;

    const int prep_n = (NF + H) * G4 + H * NOUT;
    prep_kernel<<<(prep_n + 255) / 256, 256>>>(W_ih, W_hh, W_out);

    cudaFuncSetAttribute(lstm_kernel,
                         cudaFuncAttributeMaxDynamicSharedMemorySize, SMEM_BYTES);
    lstm_kernel<<<NCTA, NTHR, SMEM_BYTES>>>(x, b_ih, b_hh, b_out, out);
}

// round 14
// speedup vs baseline: 1.5820x; 1.0385x over previous
#include <cuda_runtime.h>
#include <cstdint>

// Problem constants
#define BATCH 1024
#define SEQ   512
#define NF    64
#define H     128
#define G4    512
#define NOUT  128

// Kernel config
#define M     8
#define NCTA  128
#define NTHR  512
#define RESK  8                // resident Whh rows per kgroup

// smem layout (floats)
#define OFF_WIH   0                        // [64][512]
#define OFF_WHH   (64 * G4)                // [16][512]: 0..7 = Whh[0..7], 8..15 = Whh[64..71]
#define OFF_XD    (OFF_WHH + 16 * G4)      // [2][64][8]
#define OFF_HD    (OFF_XD + 2 * NF * M)    // [128][8]
#define OFF_PART  (OFF_HD + H * M)         // [2][8][512] floats (raw gate partials)
#define SMEM_FLOATS (OFF_PART + 2 * 8 * G4)   // 51200
#define SMEM_BYTES  (SMEM_FLOATS * 4)         // 204800

typedef unsigned long long ull;

__device__ float g_WihT[NF * G4];          // [f][c]
__device__ float g_WhhT[(H + 8) * G4];     // [k][c], +8 pad rows for ring overfetch
__device__ float g_WoutT[H * NOUT];        // [k][oc]

// ---------------- packed f32x2 helpers ----------------
__device__ __forceinline__ void ffma2(ull& acc, ull a, ull b) {
    asm("fma.rn.f32x2 %0, %1, %2, %0;" : "+l"(acc) : "l"(a), "l"(b));
}
__device__ __forceinline__ ull pack2(float lo, float hi) {
    ull r; asm("mov.b64 %0, {%1, %2};" : "=l"(r) : "f"(lo), "f"(hi)); return r;
}
__device__ __forceinline__ void unpack2(ull v, float& lo, float& hi) {
    asm("mov.b64 {%0, %1}, %2;" : "=f"(lo), "=f"(hi) : "l"(v));
}
__device__ __forceinline__ void dup2(ull w2, ull& d0, ull& d1) {
    asm("{\n\t"
        ".reg .f32 w0, w1;\n\t"
        "mov.b64 {w0, w1}, %2;\n\t"
        "mov.b64 %0, {w0, w0};\n\t"
        "mov.b64 %1, {w1, w1};\n\t"
        "}" : "=l"(d0), "=l"(d1) : "l"(w2));
}

// ---------------- activations ----------------
__device__ __forceinline__ float ex2f(float x) { float r; asm("ex2.approx.f32 %0, %1;" : "=f"(r) : "f"(x)); return r; }
__device__ __forceinline__ float rcpf(float x) { float r; asm("rcp.approx.f32 %0, %1;" : "=f"(r) : "f"(x)); return r; }
__device__ __forceinline__ float sigmf(float x) {
    return rcpf(1.0f + ex2f(-1.4426950408889634f * x));
}
__device__ __forceinline__ float tanhf_acc(float x) {
    return fmaf(2.0f, rcpf(1.0f + ex2f(-2.8853900817779268f * x)), -1.0f);
}

// ---------------- one-time weight transpose ----------------
__global__ void prep_kernel(const float* __restrict__ W_ih,
                            const float* __restrict__ W_hh,
                            const float* __restrict__ W_out) {
    int idx = blockIdx.x * blockDim.x + threadIdx.x;
    if (idx < (NF + H) * G4) {
        int k = idx / G4;
        int c = idx - k * G4;
        if (k < NF) g_WihT[idx]               = W_ih[c * NF + k];
        else        g_WhhT[(k - NF) * G4 + c] = W_hh[c * H + (k - NF)];
    } else {
        int j = idx - (NF + H) * G4;
        if (j < H * NOUT) {
            int k = j >> 7, oc = j & 127;
            g_WoutT[k * NOUT + oc] = W_out[oc * H + k];
        }
    }
}

// row-packed micro-step: q0..q3 = col c0 rowpairs, r0..r3 = col c0+1 rowpairs
#define STEPW(W2, SRC)                                                  \
    do {                                                                \
        ull d0, d1; dup2((W2), d0, d1);                                 \
        ulonglong2 hA = *(const ulonglong2*)(SRC);                      \
        ulonglong2 hB = *(const ulonglong2*)((SRC) + 4);                \
        ffma2(q0, hA.x, d0); ffma2(q1, hA.y, d0);                       \
        ffma2(q2, hB.x, d0); ffma2(q3, hB.y, d0);                       \
        ffma2(r0, hA.x, d1); ffma2(r1, hA.y, d1);                       \
        ffma2(r2, hB.x, d1); ffma2(r3, hB.y, d1);                       \
    } while (0)

// ---------------- persistent fused LSTM kernel ----------------
__global__ void __launch_bounds__(NTHR, 1)
lstm_kernel(const float* __restrict__ x,
            const float* __restrict__ b_ih, const float* __restrict__ b_hh,
            const float* __restrict__ b_out,
            float* __restrict__ out)
{
    extern __shared__ float sm[];
    float* Wih  = sm + OFF_WIH;
    float* Whh  = sm + OFF_WHH;
    float* xd   = sm + OFF_XD;             // [2][64][8]
    float* hd   = sm + OFF_HD;             // [128][8]
    float* pf   = sm + OFF_PART;           // [2][8][512]
    ull*   pu   = (ull*)pf;                // [2][8][256]

    const int tid = threadIdx.x;
    const int bbase = blockIdx.x * M;

    const int cp = tid & 255;
    const int c0 = 2 * cp;
    const int kg = tid >> 8;               // 0: x[0,32)+h[0,64) ; 1: x[32,64)+h[64,128)

    // ---- stage resident weights ----
    {
        const float4* s = (const float4*)g_WihT;
        float4*       d = (float4*)Wih;
        #pragma unroll
        for (int i = 0; i < (NF * G4 / 4) / NTHR; ++i) d[tid + i * NTHR] = s[tid + i * NTHR];
    }
    {   // sm rows 0..7 = Whh[0..7]; sm rows 8..15 = Whh[64..71]
        float4* d = (float4*)Whh;
        const float4* s0 = (const float4*)(g_WhhT);
        const float4* s1 = (const float4*)(g_WhhT + 64 * G4);
        for (int i = tid; i < RESK * G4 / 4; i += NTHR) {
            d[i]                  = s0[i];
            d[RESK * G4 / 4 + i]  = s1[i];
        }
    }
    for (int i = tid; i < H * M; i += NTHR) hd[i] = 0.0f;

    // x loader: feature lf = tid>>3, row lr = tid&7
    const int lf = tid >> 3, lr = tid & 7;
    const float* xp = x + ((size_t)(bbase + lr) * SEQ) * NF + lf;
    xd[lf * M + lr] = xp[0];               // buffer 0, t=0

    // bias (kg0 only)
    ull bias0 = 0ull, bias1 = 0ull;
    if (kg == 0) {
        float bb0 = b_ih[c0] + b_hh[c0];
        float bb1 = b_ih[c0 + 1] + b_hh[c0 + 1];
        bias0 = pack2(bb0, bb0);
        bias1 = pack2(bb1, bb1);
    }

    // phase-2 identity: col hc, rows rb, rb+1
    const int hc = tid & 127;
    const int rb = (tid >> 7) * 2;
    float cs0 = 0.f, cs1 = 0.f;

    const int xbase = kg * 32;             // x rows for this kgroup
    const int hbase = kg * 64;             // h rows for this kgroup
    const ull* wring0 = (const ull*)(g_WhhT + (kg ? 72 : 8) * G4) + cp;  // stream base

    __syncthreads();

    for (int t = 0; t < SEQ; ++t) {
        // prefetch x(t+1)
        float xpre = 0.f;
        const bool doPre = (t + 1 < SEQ);
        if (doPre) xpre = __ldg(xp + (size_t)(t + 1) * NF);

        // ring preload for this iter's streamed h rows (consumed after B1 — long cover)
        const ull* wg = wring0;
        ull u0 = __ldg(wg + 0 * 256), u1 = __ldg(wg + 1 * 256),
            u2 = __ldg(wg + 2 * 256), u3 = __ldg(wg + 3 * 256),
            u4 = __ldg(wg + 4 * 256), u5 = __ldg(wg + 5 * 256),
            u6 = __ldg(wg + 6 * 256), u7 = __ldg(wg + 7 * 256);
        wg += 8 * 256;

        // phase 2 for step t-1 (overlaps x-part issue from other warps)
        if (t > 0) {
            const float* pp0 = pf + rb * G4;
            const float* pp1 = pf + (8 + rb) * G4;
            float si0 = pp0[hc]       + pp1[hc];
            float sf0 = pp0[hc + 128] + pp1[hc + 128];
            float sg0 = pp0[hc + 256] + pp1[hc + 256];
            float so0 = pp0[hc + 384] + pp1[hc + 384];
            const float* qq0 = pp0 + G4;
            const float* qq1 = pp1 + G4;
            float si1 = qq0[hc]       + qq1[hc];
            float sf1 = qq0[hc + 128] + qq1[hc + 128];
            float sg1 = qq0[hc + 256] + qq1[hc + 256];
            float so1 = qq0[hc + 384] + qq1[hc + 384];

            float iv0 = sigmf(si0), fv0 = sigmf(sf0), gv0 = tanhf_acc(sg0), ov0 = sigmf(so0);
            float iv1 = sigmf(si1), fv1 = sigmf(sf1), gv1 = tanhf_acc(sg1), ov1 = sigmf(so1);
            cs0 = fmaf(fv0, cs0, iv0 * gv0);
            cs1 = fmaf(fv1, cs1, iv1 * gv1);
            float h0 = ov0 * tanhf_acc(cs0);
            float h1 = ov1 * tanhf_acc(cs1);
            *(ull*)(hd + hc * M + rb) = pack2(h0, h1);
        }

        // accumulators
        ull q0 = bias0, q1 = bias0, q2 = bias0, q3 = bias0;
        ull r0 = bias1, r1 = bias1, r2 = bias1, r3 = bias1;

        // x-part: 32 rows, weights resident
        const float* xsb = xd + (t & 1) * (NF * M);
        #pragma unroll 8
        for (int j = 0; j < 32; ++j) {
            ull w2 = *(const ull*)(Wih + (xbase + j) * G4 + c0);
            STEPW(w2, xsb + (xbase + j) * M);
        }

        __syncthreads();   // B1: hd(t-1) complete, visible to all

        // h-part: 8 resident rows
        #pragma unroll
        for (int k = 0; k < RESK; ++k) {
            ull w2 = *(const ull*)(Whh + (kg * RESK + k) * G4 + c0);
            STEPW(w2, hd + (hbase + k) * M);
        }
        // h-part: 56 streamed rows, depth-8 ring (overfetch rows valid/padded)
        #pragma unroll
        for (int k = RESK; k < 64; k += 8) {
            STEPW(u0, hd + (hbase + k + 0) * M); u0 = __ldg(wg + 0 * 256);
            STEPW(u1, hd + (hbase + k + 1) * M); u1 = __ldg(wg + 1 * 256);
            STEPW(u2, hd + (hbase + k + 2) * M); u2 = __ldg(wg + 2 * 256);
            STEPW(u3, hd + (hbase + k + 3) * M); u3 = __ldg(wg + 3 * 256);
            STEPW(u4, hd + (hbase + k + 4) * M); u4 = __ldg(wg + 4 * 256);
            STEPW(u5, hd + (hbase + k + 5) * M); u5 = __ldg(wg + 5 * 256);
            STEPW(u6, hd + (hbase + k + 6) * M); u6 = __ldg(wg + 6 * 256);
            STEPW(u7, hd + (hbase + k + 7) * M); u7 = __ldg(wg + 7 * 256);
            wg += 8 * 256;
        }

        // transpose accumulators and store raw partials: pf[kg][row][col]
        {
            ull* pb = pu + kg * 8 * 256 + cp;
            float x0, x1, y0, y1;
            unpack2(q0, x0, x1); unpack2(r0, y0, y1);
            pb[0 * 256] = pack2(x0, y0); pb[1 * 256] = pack2(x1, y1);
            unpack2(q1, x0, x1); unpack2(r1, y0, y1);
            pb[2 * 256] = pack2(x0, y0); pb[3 * 256] = pack2(x1, y1);
            unpack2(q2, x0, x1); unpack2(r2, y0, y1);
            pb[4 * 256] = pack2(x0, y0); pb[5 * 256] = pack2(x1, y1);
            unpack2(q3, x0, x1); unpack2(r3, y0, y1);
            pb[6 * 256] = pack2(x0, y0); pb[7 * 256] = pack2(x1, y1);
        }
        // stage x(t+1)
        if (doPre) xd[((t + 1) & 1) * (NF * M) + lf * M + lr] = xpre;

        __syncthreads();   // B2: partials(t) + xd(t+1) visible
    }

    // final phase 2 (t = SEQ-1)
    {
        const float* pp0 = pf + rb * G4;
        const float* pp1 = pf + (8 + rb) * G4;
        float si0 = pp0[hc]       + pp1[hc];
        float sf0 = pp0[hc + 128] + pp1[hc + 128];
        float sg0 = pp0[hc + 256] + pp1[hc + 256];
        float so0 = pp0[hc + 384] + pp1[hc + 384];
        const float* qq0 = pp0 + G4;
        const float* qq1 = pp1 + G4;
        float si1 = qq0[hc]       + qq1[hc];
        float sf1 = qq0[hc + 128] + qq1[hc + 128];
        float sg1 = qq0[hc + 256] + qq1[hc + 256];
        float so1 = qq0[hc + 384] + qq1[hc + 384];

        float iv0 = sigmf(si0), fv0 = sigmf(sf0), gv0 = tanhf_acc(sg0), ov0 = sigmf(so0);
        float iv1 = sigmf(si1), fv1 = sigmf(sf1), gv1 = tanhf_acc(sg1), ov1 = sigmf(so1);
        cs0 = fmaf(fv0, cs0, iv0 * gv0);
        cs1 = fmaf(fv1, cs1, iv1 * gv1);
        hd[hc * M + rb]     = ov0 * tanhf_acc(cs0);
        hd[hc * M + rb + 1] = ov1 * tanhf_acc(cs1);
    }
    __syncthreads();

    // output projection: thread (oc, rows rr, rr+4)
    {
        const int oc = tid & 127;
        const int rr = tid >> 7;
        float acc0 = b_out[oc], acc1 = acc0;
        const float* wt = g_WoutT + oc;
        #pragma unroll 8
        for (int k = 0; k < H; ++k) {
            float w = __ldg(wt + k * NOUT);
            acc0 = fmaf(w, hd[k * M + rr], acc0);
            acc1 = fmaf(w, hd[k * M + rr + 4], acc1);
        }
        out[(size_t)(bbase + rr) * NOUT + oc]     = acc0;
        out[(size_t)(bbase + rr + 4) * NOUT + oc] = acc1;
    }
}

extern "C" void kernel_launch(void* const* d_in, const int* in_sizes, int n_in,
                              void* d_out, int out_size)
{
    const float* x     = (const float*)d_in[0];
    const float* W_ih  = (const float*)d_in[1];
    const float* W_hh  = (const float*)d_in[2];
    const float* b_ih  = (const float*)d_in[3];
    const float* b_hh  = (const float*)d_in[4];
    const float* W_out = (const float*)d_in[5];
    const float* b_out = (const float*)d_in[6];
    float* out = (float*)d_out;

    const int prep_n = (NF + H) * G4 + H * NOUT;
    prep_kernel<<<(prep_n + 255) / 256, 256>>>(W_ih, W_hh, W_out);

    cudaFuncSetAttribute(lstm_kernel,
                         cudaFuncAttributeMaxDynamicSharedMemorySize, SMEM_BYTES);
    lstm_kernel<<<NCTA, NTHR, SMEM_BYTES>>>(x, b_ih, b_hh, b_out, out);
}

// round 15
// speedup vs baseline: 1.5954x; 1.0085x over previous
#include <cuda_runtime.h>
#include <cstdint>

// Problem constants
#define BATCH 1024
#define SEQ   512
#define NF    64
#define H     128
#define G4    512
#define NOUT  128

// Kernel config
#define M     8
#define NCTA  128
#define NTHR  1024
#define KX    16               // x-rows per kgroup (resident)
#define KH    32               // h-rows per kgroup (all streamed)

// smem layout (floats)
#define OFF_WIH   0                        // [64][512]
#define OFF_XD    (NF * G4)                // [2][64][8]
#define OFF_HD    (OFF_XD + 2 * NF * M)    // [128][8]
#define OFF_PART  (OFF_HD + H * M)         // [4][8][512] raw gate partials
#define SMEM_FLOATS (OFF_PART + 4 * 8 * G4)   // 51200
#define SMEM_BYTES  (SMEM_FLOATS * 4)         // 204800

typedef unsigned long long ull;

__device__ float g_WihT[NF * G4];          // [f][c]
__device__ float g_WhhT[(H + 8) * G4];     // [k][c], +8 pad rows for ring overfetch
__device__ float g_WoutT[H * NOUT];        // [k][oc]

// ---------------- packed f32x2 helpers ----------------
__device__ __forceinline__ void ffma2(ull& acc, ull a, ull b) {
    asm("fma.rn.f32x2 %0, %1, %2, %0;" : "+l"(acc) : "l"(a), "l"(b));
}
__device__ __forceinline__ ull pack2(float lo, float hi) {
    ull r; asm("mov.b64 %0, {%1, %2};" : "=l"(r) : "f"(lo), "f"(hi)); return r;
}
__device__ __forceinline__ void unpack2(ull v, float& lo, float& hi) {
    asm("mov.b64 {%0, %1}, %2;" : "=f"(lo), "=f"(hi) : "l"(v));
}
__device__ __forceinline__ void dup2(ull w2, ull& d0, ull& d1) {
    asm("{\n\t"
        ".reg .f32 w0, w1;\n\t"
        "mov.b64 {w0, w1}, %2;\n\t"
        "mov.b64 %0, {w0, w0};\n\t"
        "mov.b64 %1, {w1, w1};\n\t"
        "}" : "=l"(d0), "=l"(d1) : "l"(w2));
}

// ---------------- activations ----------------
__device__ __forceinline__ float ex2f(float x) { float r; asm("ex2.approx.f32 %0, %1;" : "=f"(r) : "f"(x)); return r; }
__device__ __forceinline__ float rcpf(float x) { float r; asm("rcp.approx.f32 %0, %1;" : "=f"(r) : "f"(x)); return r; }
__device__ __forceinline__ float sigmf(float x) {
    return rcpf(1.0f + ex2f(-1.4426950408889634f * x));
}
__device__ __forceinline__ float tanhf_acc(float x) {
    return fmaf(2.0f, rcpf(1.0f + ex2f(-2.8853900817779268f * x)), -1.0f);
}

// ---------------- one-time weight transpose ----------------
__global__ void prep_kernel(const float* __restrict__ W_ih,
                            const float* __restrict__ W_hh,
                            const float* __restrict__ W_out) {
    int idx = blockIdx.x * blockDim.x + threadIdx.x;
    if (idx < (NF + H) * G4) {
        int k = idx / G4;
        int c = idx - k * G4;
        if (k < NF) g_WihT[idx]               = W_ih[c * NF + k];
        else        g_WhhT[(k - NF) * G4 + c] = W_hh[c * H + (k - NF)];
    } else {
        int j = idx - (NF + H) * G4;
        if (j < H * NOUT) {
            int k = j >> 7, oc = j & 127;
            g_WoutT[k * NOUT + oc] = W_out[oc * H + k];
        }
    }
}

// row-packed micro-step: q0..q3 = col c0 rowpairs, r0..r3 = col c0+1 rowpairs
#define STEPW(W2, SRC)                                                  \
    do {                                                                \
        ull d0, d1; dup2((W2), d0, d1);                                 \
        ulonglong2 hA = *(const ulonglong2*)(SRC);                      \
        ulonglong2 hB = *(const ulonglong2*)((SRC) + 4);                \
        ffma2(q0, hA.x, d0); ffma2(q1, hA.y, d0);                       \
        ffma2(q2, hB.x, d0); ffma2(q3, hB.y, d0);                       \
        ffma2(r0, hA.x, d1); ffma2(r1, hA.y, d1);                       \
        ffma2(r2, hB.x, d1); ffma2(r3, hB.y, d1);                       \
    } while (0)

// ---------------- persistent fused LSTM kernel ----------------
__global__ void __launch_bounds__(NTHR, 1)
lstm_kernel(const float* __restrict__ x,
            const float* __restrict__ b_ih, const float* __restrict__ b_hh,
            const float* __restrict__ b_out,
            float* __restrict__ out)
{
    extern __shared__ float sm[];
    float* Wih = sm + OFF_WIH;
    float* xd  = sm + OFF_XD;              // [2][64][8]
    float* hd  = sm + OFF_HD;              // [128][8]
    float* pf  = sm + OFF_PART;            // [4][8][512]
    ull*   pu  = (ull*)pf;                 // [4][8][256]

    const int tid = threadIdx.x;
    const int bbase = blockIdx.x * M;

    const int cp = tid & 255;
    const int c0 = 2 * cp;
    const int kg = tid >> 8;               // 0..3

    const int xbase = kg * KX;             // x rows [xbase, xbase+16)
    const int hbase = kg * KH;             // h rows [hbase, hbase+32)

    // ---- stage Wih (coalesced) ----
    {
        const float4* s = (const float4*)g_WihT;
        float4*       d = (float4*)Wih;
        #pragma unroll
        for (int i = 0; i < (NF * G4 / 4) / NTHR; ++i) d[tid + i * NTHR] = s[tid + i * NTHR];
    }
    if (tid < H * M) hd[tid] = 0.0f;

    // x loader (tid < 512): feature lf, row lr
    const int lf = tid >> 3, lr = tid & 7;
    const float* xp = x + ((size_t)(bbase + lr) * SEQ) * NF + lf;
    if (tid < 512) xd[lf * M + lr] = xp[0];   // buffer 0, t=0

    // bias (kg0 only)
    ull bias0 = 0ull, bias1 = 0ull;
    if (kg == 0) {
        float bb0 = b_ih[c0] + b_hh[c0];
        float bb1 = b_ih[c0 + 1] + b_hh[c0 + 1];
        bias0 = pack2(bb0, bb0);
        bias1 = pack2(bb1, bb1);
    }

    // phase-2 identity: one state per thread (col hc, row prow)
    const int hc = tid & 127;
    const int prow = tid >> 7;             // 0..7
    float cs = 0.f;

    const ull* wring0 = (const ull*)(g_WhhT + hbase * G4) + cp;

    __syncthreads();

    for (int t = 0; t < SEQ; ++t) {
        // prefetch x(t+1)
        float xpre = 0.f;
        const bool doPre = (tid < 512) && (t + 1 < SEQ);
        if (doPre) xpre = __ldg(xp + (size_t)(t + 1) * NF);

        // ring preload (consumed after B1 — long cover)
        const ull* wg = wring0;
        ull u0 = __ldg(wg + 0 * 256), u1 = __ldg(wg + 1 * 256),
            u2 = __ldg(wg + 2 * 256), u3 = __ldg(wg + 3 * 256);
        wg += 4 * 256;

        // phase 2 for step t-1 (overlaps x-part issue from other warps)
        if (t > 0) {
            const float* pr = pf + prow * G4;
            float si = pr[hc]               + pr[8 * G4 + hc]
                     + pr[16 * G4 + hc]     + pr[24 * G4 + hc];
            float sf = pr[hc + 128]         + pr[8 * G4 + hc + 128]
                     + pr[16 * G4 + hc + 128] + pr[24 * G4 + hc + 128];
            float sg = pr[hc + 256]         + pr[8 * G4 + hc + 256]
                     + pr[16 * G4 + hc + 256] + pr[24 * G4 + hc + 256];
            float so = pr[hc + 384]         + pr[8 * G4 + hc + 384]
                     + pr[16 * G4 + hc + 384] + pr[24 * G4 + hc + 384];
            float iv = sigmf(si), fv = sigmf(sf), gv = tanhf_acc(sg), ov = sigmf(so);
            cs = fmaf(fv, cs, iv * gv);
            hd[hc * M + prow] = ov * tanhf_acc(cs);
        }

        // accumulators
        ull q0 = bias0, q1 = bias0, q2 = bias0, q3 = bias0;
        ull r0 = bias1, r1 = bias1, r2 = bias1, r3 = bias1;

        // x-part: 16 rows, weights resident
        const float* xsb = xd + (t & 1) * (NF * M);
        #pragma unroll
        for (int j = 0; j < KX; ++j) {
            ull w2 = *(const ull*)(Wih + (xbase + j) * G4 + c0);
            STEPW(w2, xsb + (xbase + j) * M);
        }

        __syncthreads();   // B1: hd(t-1) complete

        // h-part: 32 streamed rows, ring-4 (overfetch 4 rows: next kg / pad)
        #pragma unroll
        for (int k = 0; k < KH; k += 4) {
            STEPW(u0, hd + (hbase + k + 0) * M); u0 = __ldg(wg + 0 * 256);
            STEPW(u1, hd + (hbase + k + 1) * M); u1 = __ldg(wg + 1 * 256);
            STEPW(u2, hd + (hbase + k + 2) * M); u2 = __ldg(wg + 2 * 256);
            STEPW(u3, hd + (hbase + k + 3) * M); u3 = __ldg(wg + 3 * 256);
            wg += 4 * 256;
        }

        // transpose accumulators, store raw partials pf[kg][row][col]
        {
            ull* pb = pu + kg * 8 * 256 + cp;
            float x0, x1, y0, y1;
            unpack2(q0, x0, x1); unpack2(r0, y0, y1);
            pb[0 * 256] = pack2(x0, y0); pb[1 * 256] = pack2(x1, y1);
            unpack2(q1, x0, x1); unpack2(r1, y0, y1);
            pb[2 * 256] = pack2(x0, y0); pb[3 * 256] = pack2(x1, y1);
            unpack2(q2, x0, x1); unpack2(r2, y0, y1);
            pb[4 * 256] = pack2(x0, y0); pb[5 * 256] = pack2(x1, y1);
            unpack2(q3, x0, x1); unpack2(r3, y0, y1);
            pb[6 * 256] = pack2(x0, y0); pb[7 * 256] = pack2(x1, y1);
        }
        // stage x(t+1)
        if (doPre) xd[((t + 1) & 1) * (NF * M) + lf * M + lr] = xpre;

        __syncthreads();   // B2: partials(t) + xd(t+1) visible
    }

    // final phase 2 (t = SEQ-1)
    {
        const float* pr = pf + prow * G4;
        float si = pr[hc]               + pr[8 * G4 + hc]
                 + pr[16 * G4 + hc]     + pr[24 * G4 + hc];
        float sf = pr[hc + 128]         + pr[8 * G4 + hc + 128]
                 + pr[16 * G4 + hc + 128] + pr[24 * G4 + hc + 128];
        float sg = pr[hc + 256]         + pr[8 * G4 + hc + 256]
                 + pr[16 * G4 + hc + 256] + pr[24 * G4 + hc + 256];
        float so = pr[hc + 384]         + pr[8 * G4 + hc + 384]
                 + pr[16 * G4 + hc + 384] + pr[24 * G4 + hc + 384];
        float iv = sigmf(si), fv = sigmf(sf), gv = tanhf_acc(sg), ov = sigmf(so);
        cs = fmaf(fv, cs, iv * gv);
        hd[hc * M + prow] = ov * tanhf_acc(cs);
    }
    __syncthreads();

    // output projection: one (row, oc) per thread
    {
        const int oc = hc;
        const int rr = prow;
        float acc = b_out[oc];
        const float* wt = g_WoutT + oc;
        #pragma unroll 8
        for (int k = 0; k < H; ++k) {
            acc = fmaf(__ldg(wt + k * NOUT), hd[k * M + rr], acc);
        }
        out[(size_t)(bbase + rr) * NOUT + oc] = acc;
    }
}

extern "C" void kernel_launch(void* const* d_in, const int* in_sizes, int n_in,
                              void* d_out, int out_size)
{
    const float* x     = (const float*)d_in[0];
    const float* W_ih  = (const float*)d_in[1];
    const float* W_hh  = (const float*)d_in[2];
    const float* b_ih  = (const float*)d_in[3];
    const float* b_hh  = (const float*)d_in[4];
    const float* W_out = (const float*)d_in[5];
    const float* b_out = (const float*)d_in[6];
    float* out = (float*)d_out;

    const int prep_n = (NF + H) * G4 + H * NOUT;
    prep_kernel<<<(prep_n + 255) / 256, 256>>>(W_ih, W_hh, W_out);

    cudaFuncSetAttribute(lstm_kernel,
                         cudaFuncAttributeMaxDynamicSharedMemorySize, SMEM_BYTES);
    lstm_kernel<<<NCTA, NTHR, SMEM_BYTES>>>(x, b_ih, b_hh, b_out, out);
}